// round 3
// baseline (speedup 1.0000x reference)
#include <cuda_runtime.h>
#include <math.h>

#define B_  2
#define T_  2048
#define C_  768
#define H_  12
#define HD_ 64
#define BT_ (B_*T_)   // 4096

static __device__ float g_ln[BT_ * C_];          // layernorm output (reused ln1/ln2)
static __device__ float g_qkv[BT_ * 3 * C_];     // qkv projections
static __device__ float g_att[BT_ * C_];         // attention output (pre-proj)
static __device__ float g_x2[BT_ * C_];          // x + attn branch
static __device__ float g_hbuf[BT_ * 4 * C_];    // gelu(fc) activations

// ---------------------------------------------------------------------------
// LayerNorm: one block per row (C=768 = 3*256)
// ---------------------------------------------------------------------------
__global__ void ln_kernel(const float* __restrict__ x, const float* __restrict__ g,
                          const float* __restrict__ bia, float* __restrict__ out) {
    int row = blockIdx.x;
    const float* xr = x + (size_t)row * C_;
    int t = threadIdx.x;
    float v0 = xr[t], v1 = xr[t + 256], v2 = xr[t + 512];
    float s = v0 + v1 + v2;
    float ss = v0 * v0 + v1 * v1 + v2 * v2;
    #pragma unroll
    for (int m = 16; m; m >>= 1) {
        s  += __shfl_xor_sync(0xffffffffu, s,  m);
        ss += __shfl_xor_sync(0xffffffffu, ss, m);
    }
    __shared__ float sm1[8], sm2[8];
    int w = t >> 5, l = t & 31;
    if (l == 0) { sm1[w] = s; sm2[w] = ss; }
    __syncthreads();
    if (w == 0) {
        s = sm1[l & 7]; ss = sm2[l & 7];
        #pragma unroll
        for (int m = 4; m; m >>= 1) {
            s  += __shfl_xor_sync(0xffffffffu, s,  m);
            ss += __shfl_xor_sync(0xffffffffu, ss, m);
        }
        if (l == 0) { sm1[0] = s; sm2[0] = ss; }
    }
    __syncthreads();
    float mean = sm1[0] * (1.0f / C_);
    float var  = sm2[0] * (1.0f / C_) - mean * mean;
    float inv  = rsqrtf(var + 1e-5f);
    float* orow = out + (size_t)row * C_;
    orow[t]       = (v0 - mean) * inv * g[t]       + bia[t];
    orow[t + 256] = (v1 - mean) * inv * g[t + 256] + bia[t + 256];
    orow[t + 512] = (v2 - mean) * inv * g[t + 512] + bia[t + 512];
}

// ---------------------------------------------------------------------------
// SGEMM: C = A[M,K] @ B[K,N], 128x128 block tile, BK=16, 8x8 per thread.
// Register-prefetch pipeline: global loads for tile k+1 issued before the
// compute of tile k, so the LDG latency overlaps 16 k-steps of FFMA.
// EPI: 0 = plain, 1 = +Res (residual), 2 = exact GELU.
// All M,N multiples of 128; K multiple of 16.
// ---------------------------------------------------------------------------
template <int EPI>
__global__ void __launch_bounds__(256, 2)
sgemm_kernel(const float* __restrict__ A, const float* __restrict__ Bm,
             const float* __restrict__ Res, float* __restrict__ Cm,
             int M, int N, int K) {
    __shared__ float As[16][132];   // [k][m], padded
    __shared__ float Bs[16][128];   // [k][n]
    int tid = threadIdx.x;
    int tx = tid & 15, ty = tid >> 4;
    int bm = blockIdx.y, bn = blockIdx.x;
    const float* Ab = A  + (size_t)bm * 128 * K;
    const float* Bb = Bm + (size_t)bn * 128;

    float acc[8][8];
    #pragma unroll
    for (int i = 0; i < 8; i++)
        #pragma unroll
        for (int j = 0; j < 8; j++) acc[i][j] = 0.f;

    int arow = tid >> 2;            // 0..63
    int acol = (tid & 3) * 4;       // 0,4,8,12
    int brow = tid >> 5;            // 0..7
    int bcol = (tid & 31) * 4;      // 0..124

    // prefetch first tile into registers
    float4 a0 = *(const float4*)(Ab + (size_t)arow * K + acol);
    float4 a1 = *(const float4*)(Ab + (size_t)(arow + 64) * K + acol);
    float4 b0 = *(const float4*)(Bb + (size_t)brow * N + bcol);
    float4 b1 = *(const float4*)(Bb + (size_t)(brow + 8) * N + bcol);

    for (int kt = 0; kt < K; kt += 16) {
        // deposit current tile into smem
        As[acol + 0][arow] = a0.x; As[acol + 1][arow] = a0.y;
        As[acol + 2][arow] = a0.z; As[acol + 3][arow] = a0.w;
        As[acol + 0][arow + 64] = a1.x; As[acol + 1][arow + 64] = a1.y;
        As[acol + 2][arow + 64] = a1.z; As[acol + 3][arow + 64] = a1.w;
        *(float4*)&Bs[brow][bcol]     = b0;
        *(float4*)&Bs[brow + 8][bcol] = b1;
        __syncthreads();

        // issue global loads for NEXT tile before computing this one
        int kn = kt + 16;
        if (kn < K) {
            a0 = *(const float4*)(Ab + (size_t)arow * K + kn + acol);
            a1 = *(const float4*)(Ab + (size_t)(arow + 64) * K + kn + acol);
            b0 = *(const float4*)(Bb + (size_t)(kn + brow) * N + bcol);
            b1 = *(const float4*)(Bb + (size_t)(kn + brow + 8) * N + bcol);
        }

        #pragma unroll
        for (int k = 0; k < 16; k++) {
            float4 av0 = *(const float4*)&As[k][ty * 8];
            float4 av1 = *(const float4*)&As[k][ty * 8 + 4];
            float4 bv0 = *(const float4*)&Bs[k][tx * 4];        // cols tx*4..+3
            float4 bv1 = *(const float4*)&Bs[k][64 + tx * 4];   // cols 64+tx*4..+3
            float a[8] = {av0.x, av0.y, av0.z, av0.w, av1.x, av1.y, av1.z, av1.w};
            float b[8] = {bv0.x, bv0.y, bv0.z, bv0.w, bv1.x, bv1.y, bv1.z, bv1.w};
            #pragma unroll
            for (int i = 0; i < 8; i++)
                #pragma unroll
                for (int j = 0; j < 8; j++) acc[i][j] += a[i] * b[j];
        }
        __syncthreads();
    }

    // epilogue: fully-coalesced float4 stores (cols tx*4 and 64+tx*4)
    int crow0 = bm * 128 + ty * 8;
    int ccolA = bn * 128 + tx * 4;
    int ccolB = ccolA + 64;
    #pragma unroll
    for (int i = 0; i < 8; i++) {
        size_t offA = (size_t)(crow0 + i) * N + ccolA;
        size_t offB = (size_t)(crow0 + i) * N + ccolB;
        float4 va = make_float4(acc[i][0], acc[i][1], acc[i][2], acc[i][3]);
        float4 vb = make_float4(acc[i][4], acc[i][5], acc[i][6], acc[i][7]);
        if (EPI == 1) {
            float4 ra = *(const float4*)(Res + offA);
            float4 rb = *(const float4*)(Res + offB);
            va.x += ra.x; va.y += ra.y; va.z += ra.z; va.w += ra.w;
            vb.x += rb.x; vb.y += rb.y; vb.z += rb.z; vb.w += rb.w;
        }
        if (EPI == 2) {
            va.x = 0.5f * va.x * (1.f + erff(va.x * 0.70710678118f));
            va.y = 0.5f * va.y * (1.f + erff(va.y * 0.70710678118f));
            va.z = 0.5f * va.z * (1.f + erff(va.z * 0.70710678118f));
            va.w = 0.5f * va.w * (1.f + erff(va.w * 0.70710678118f));
            vb.x = 0.5f * vb.x * (1.f + erff(vb.x * 0.70710678118f));
            vb.y = 0.5f * vb.y * (1.f + erff(vb.y * 0.70710678118f));
            vb.z = 0.5f * vb.z * (1.f + erff(vb.z * 0.70710678118f));
            vb.w = 0.5f * vb.w * (1.f + erff(vb.w * 0.70710678118f));
        }
        *(float4*)(Cm + offA) = va;
        *(float4*)(Cm + offB) = vb;
    }
}

// ---------------------------------------------------------------------------
// Flash attention (fp32): grid (T/64, H, B), 256 threads (16x16), 64-row Q tile.
// Streams 64-row K/V tiles with online softmax. qkv layout: [BT, 3C].
// ---------------------------------------------------------------------------
#define ATTN_SMEM ((3 * 64 * 68 + 64 * 65) * 4)

__global__ void __launch_bounds__(256, 2)
attn_kernel(const float* __restrict__ qkv, float* __restrict__ out) {
    extern __shared__ float smem[];
    float* Qt = smem;                 // [64 d][68]  (d-major, transposed)
    float* Kt = Qt + 64 * 68;         // [64 d][68]
    float* Vs = Kt + 64 * 68;         // [64 c][68]  (row-major)
    float* St = Vs + 64 * 68;         // [64 c][65]  (transposed P)

    int qt = blockIdx.x, h = blockIdx.y, b = blockIdx.z;
    int tid = threadIdx.x, tx = tid & 15, ty = tid >> 4;
    int qbase = qt * 64;
    const size_t rs = 3 * C_;
    const float* qptr = qkv + (size_t)b * T_ * rs + h * HD_;
    const float* kptr = qptr + C_;
    const float* vptr = qptr + 2 * C_;

    // load Q tile transposed: Qt[d][r]
    {
        int r = tid >> 4;             // 0..15
        int d = (tid & 15) * 4;       // 0..60
        #pragma unroll
        for (int i = 0; i < 4; i++) {
            int rr = r + 16 * i;
            float4 q4 = *(const float4*)(qptr + (size_t)(qbase + rr) * rs + d);
            Qt[(d + 0) * 68 + rr] = q4.x; Qt[(d + 1) * 68 + rr] = q4.y;
            Qt[(d + 2) * 68 + rr] = q4.z; Qt[(d + 3) * 68 + rr] = q4.w;
        }
    }

    float m_[4], l_[4], o[4][4];
    #pragma unroll
    for (int i = 0; i < 4; i++) {
        m_[i] = -1e30f; l_[i] = 0.f;
        #pragma unroll
        for (int j = 0; j < 4; j++) o[i][j] = 0.f;
    }
    int r0 = ty * 4, c0 = tx * 4;

    for (int kt = 0; kt <= qt; kt++) {
        int kbase = kt * 64;
        __syncthreads();   // prior PV reads of Kt/Vs/St complete
        {
            int r = tid >> 4;
            int d = (tid & 15) * 4;
            #pragma unroll
            for (int i = 0; i < 4; i++) {
                int rr = r + 16 * i;
                float4 k4 = *(const float4*)(kptr + (size_t)(kbase + rr) * rs + d);
                Kt[(d + 0) * 68 + rr] = k4.x; Kt[(d + 1) * 68 + rr] = k4.y;
                Kt[(d + 2) * 68 + rr] = k4.z; Kt[(d + 3) * 68 + rr] = k4.w;
                float4 v4 = *(const float4*)(vptr + (size_t)(kbase + rr) * rs + d);
                *(float4*)&Vs[rr * 68 + d] = v4;
            }
        }
        __syncthreads();

        // S = Q @ K^T (4x4 per thread)
        float s[4][4];
        #pragma unroll
        for (int i = 0; i < 4; i++)
            #pragma unroll
            for (int j = 0; j < 4; j++) s[i][j] = 0.f;
        #pragma unroll 4
        for (int d = 0; d < 64; d++) {
            float4 q4 = *(const float4*)&Qt[d * 68 + r0];
            float4 k4 = *(const float4*)&Kt[d * 68 + c0];
            float qa[4] = {q4.x, q4.y, q4.z, q4.w};
            float ka[4] = {k4.x, k4.y, k4.z, k4.w};
            #pragma unroll
            for (int i = 0; i < 4; i++)
                #pragma unroll
                for (int j = 0; j < 4; j++) s[i][j] += qa[i] * ka[j];
        }
        bool diag = (kt == qt);
        #pragma unroll
        for (int i = 0; i < 4; i++)
            #pragma unroll
            for (int j = 0; j < 4; j++) {
                s[i][j] *= 0.125f;  // 1/sqrt(64)
                if (diag && (c0 + j) > (r0 + i)) s[i][j] = -1e30f;
            }

        // online softmax update (row stats replicated across the 16 tx lanes)
        #pragma unroll
        for (int i = 0; i < 4; i++) {
            float mx = fmaxf(fmaxf(s[i][0], s[i][1]), fmaxf(s[i][2], s[i][3]));
            #pragma unroll
            for (int msk = 8; msk; msk >>= 1)
                mx = fmaxf(mx, __shfl_xor_sync(0xffffffffu, mx, msk));
            float mnew  = fmaxf(m_[i], mx);
            float alpha = expf(m_[i] - mnew);
            float rsum = 0.f;
            #pragma unroll
            for (int j = 0; j < 4; j++) {
                float p = expf(s[i][j] - mnew);
                s[i][j] = p; rsum += p;
            }
            #pragma unroll
            for (int msk = 8; msk; msk >>= 1)
                rsum += __shfl_xor_sync(0xffffffffu, rsum, msk);
            l_[i] = l_[i] * alpha + rsum;
            m_[i] = mnew;
            #pragma unroll
            for (int j = 0; j < 4; j++) o[i][j] *= alpha;
        }

        // store P transposed: St[c][r]
        #pragma unroll
        for (int i = 0; i < 4; i++)
            #pragma unroll
            for (int j = 0; j < 4; j++)
                St[(c0 + j) * 65 + r0 + i] = s[i][j];
        __syncthreads();

        // O += P @ V  (thread's output cols = c0..c0+3 of head dim)
        #pragma unroll 4
        for (int c = 0; c < 64; c++) {
            float p0 = St[c * 65 + r0 + 0];
            float p1 = St[c * 65 + r0 + 1];
            float p2 = St[c * 65 + r0 + 2];
            float p3 = St[c * 65 + r0 + 3];
            float4 v4 = *(const float4*)&Vs[c * 68 + c0];
            o[0][0] += p0 * v4.x; o[0][1] += p0 * v4.y; o[0][2] += p0 * v4.z; o[0][3] += p0 * v4.w;
            o[1][0] += p1 * v4.x; o[1][1] += p1 * v4.y; o[1][2] += p1 * v4.z; o[1][3] += p1 * v4.w;
            o[2][0] += p2 * v4.x; o[2][1] += p2 * v4.y; o[2][2] += p2 * v4.z; o[2][3] += p2 * v4.w;
            o[3][0] += p3 * v4.x; o[3][1] += p3 * v4.y; o[3][2] += p3 * v4.z; o[3][3] += p3 * v4.w;
        }
    }

    #pragma unroll
    for (int i = 0; i < 4; i++) {
        float inv = 1.f / l_[i];
        float4 r4 = make_float4(o[i][0] * inv, o[i][1] * inv, o[i][2] * inv, o[i][3] * inv);
        *(float4*)&out[(size_t)(b * T_ + qbase + r0 + i) * C_ + h * HD_ + c0] = r4;
    }
}

// ---------------------------------------------------------------------------
extern "C" void kernel_launch(void* const* d_in, const int* in_sizes, int n_in,
                              void* d_out, int out_size) {
    const float* x      = (const float*)d_in[0];
    const float* ln1_g  = (const float*)d_in[1];
    const float* ln1_b  = (const float*)d_in[2];
    const float* W_qkv  = (const float*)d_in[3];
    const float* W_attn = (const float*)d_in[4];
    const float* ln2_g  = (const float*)d_in[5];
    const float* ln2_b  = (const float*)d_in[6];
    const float* W_fc   = (const float*)d_in[7];
    const float* W_mlp  = (const float*)d_in[8];
    float* out = (float*)d_out;

    float *ln, *qkv, *att, *x2, *hb;
    cudaGetSymbolAddress((void**)&ln,  g_ln);
    cudaGetSymbolAddress((void**)&qkv, g_qkv);
    cudaGetSymbolAddress((void**)&att, g_att);
    cudaGetSymbolAddress((void**)&x2,  g_x2);
    cudaGetSymbolAddress((void**)&hb,  g_hbuf);

    cudaFuncSetAttribute(attn_kernel, cudaFuncAttributeMaxDynamicSharedMemorySize, ATTN_SMEM);

    // 1. ln1
    ln_kernel<<<BT_, 256>>>(x, ln1_g, ln1_b, ln);
    // 2. qkv = ln1 @ W_qkv  [4096,768]x[768,2304]
    sgemm_kernel<0><<<dim3(3 * C_ / 128, BT_ / 128), 256>>>(ln, W_qkv, nullptr, qkv, BT_, 3 * C_, C_);
    // 3. flash attention
    attn_kernel<<<dim3(T_ / 64, H_, B_), 256, ATTN_SMEM>>>(qkv, att);
    // 4. x2 = x + att @ W_attn_proj
    sgemm_kernel<1><<<dim3(C_ / 128, BT_ / 128), 256>>>(att, W_attn, x, x2, BT_, C_, C_);
    // 5. ln2
    ln_kernel<<<BT_, 256>>>(x2, ln2_g, ln2_b, ln);
    // 6. h = gelu(ln2 @ W_fc)  [4096,768]x[768,3072]
    sgemm_kernel<2><<<dim3(4 * C_ / 128, BT_ / 128), 256>>>(ln, W_fc, nullptr, hb, BT_, 4 * C_, C_);
    // 7. out = x2 + h @ W_mlp_proj  [4096,3072]x[3072,768]
    sgemm_kernel<1><<<dim3(C_ / 128, BT_ / 128), 256>>>(hb, W_mlp, x2, out, BT_, C_, 4 * C_);
}

// round 6
// speedup vs baseline: 1.6809x; 1.6809x over previous
#include <cuda_runtime.h>
#include <math.h>

#define B_  2
#define T_  2048
#define C_  768
#define H_  12
#define HD_ 64
#define BT_ (B_*T_)   // 4096

static __device__ float g_ln[BT_ * C_];          // layernorm output (reused ln1/ln2)
static __device__ float g_qkv[BT_ * 3 * C_];     // qkv projections
static __device__ float g_att[BT_ * C_];         // attention output (pre-proj)
static __device__ float g_x2[BT_ * C_];          // x + attn branch
static __device__ float g_hbuf[BT_ * 4 * C_];    // gelu(fc) activations

// ---------------------------------------------------------------------------
// helpers
// ---------------------------------------------------------------------------
__device__ __forceinline__ unsigned f2tf(float f) {
    unsigned u;
    asm("cvt.rna.tf32.f32 %0, %1;" : "=r"(u) : "f"(f));
    return u;
}

__device__ __forceinline__ void mma_tf32(float* c, const unsigned* a,
                                         unsigned b0, unsigned b1) {
    asm volatile(
        "mma.sync.aligned.m16n8k8.row.col.f32.tf32.tf32.f32 "
        "{%0,%1,%2,%3}, {%4,%5,%6,%7}, {%8,%9}, {%0,%1,%2,%3};"
        : "+f"(c[0]), "+f"(c[1]), "+f"(c[2]), "+f"(c[3])
        : "r"(a[0]), "r"(a[1]), "r"(a[2]), "r"(a[3]), "r"(b0), "r"(b1));
}

__device__ __forceinline__ float gelu_f(float v) {
    return 0.5f * v * (1.f + erff(v * 0.70710678118f));
}

// ---------------------------------------------------------------------------
// LayerNorm: one block per row (C=768 = 3*256)
// ---------------------------------------------------------------------------
__global__ void ln_kernel(const float* __restrict__ x, const float* __restrict__ g,
                          const float* __restrict__ bia, float* __restrict__ out) {
    int row = blockIdx.x;
    const float* xr = x + (size_t)row * C_;
    int t = threadIdx.x;
    float v0 = xr[t], v1 = xr[t + 256], v2 = xr[t + 512];
    float s = v0 + v1 + v2;
    float ss = v0 * v0 + v1 * v1 + v2 * v2;
    #pragma unroll
    for (int m = 16; m; m >>= 1) {
        s  += __shfl_xor_sync(0xffffffffu, s,  m);
        ss += __shfl_xor_sync(0xffffffffu, ss, m);
    }
    __shared__ float sm1[8], sm2[8];
    int w = t >> 5, l = t & 31;
    if (l == 0) { sm1[w] = s; sm2[w] = ss; }
    __syncthreads();
    if (w == 0) {
        s = sm1[l & 7]; ss = sm2[l & 7];
        #pragma unroll
        for (int m = 4; m; m >>= 1) {
            s  += __shfl_xor_sync(0xffffffffu, s,  m);
            ss += __shfl_xor_sync(0xffffffffu, ss, m);
        }
        if (l == 0) { sm1[0] = s; sm2[0] = ss; }
    }
    __syncthreads();
    float mean = sm1[0] * (1.0f / C_);
    float var  = sm2[0] * (1.0f / C_) - mean * mean;
    float inv  = rsqrtf(var + 1e-5f);
    float* orow = out + (size_t)row * C_;
    orow[t]       = (v0 - mean) * inv * g[t]       + bia[t];
    orow[t + 256] = (v1 - mean) * inv * g[t + 256] + bia[t + 256];
    orow[t + 512] = (v2 - mean) * inv * g[t + 512] + bia[t + 512];
}

// ---------------------------------------------------------------------------
// TF32 tensor-core GEMM: C = A[M,K] @ B[K,N], 128x128 block tile, BK=16.
// 8 warps in 4x2: warp tile 32(m) x 64(n) = 2 x 8 mma tiles of m16n8k8.
// fp32 global loads with register prefetch; cvt.rna -> tf32 at smem deposit.
// Smem rows padded to 136 floats (136 % 32 == 8) so fragment LDS banks are
// 8*tig+grp -> conflict-free.
// EPI: 0 = plain, 1 = +Res (residual), 2 = exact GELU.
// M,N multiples of 128; K multiple of 16.
// ---------------------------------------------------------------------------
template <int EPI>
__global__ void __launch_bounds__(256, 2)
sgemm_kernel(const float* __restrict__ A, const float* __restrict__ Bm,
             const float* __restrict__ Res, float* __restrict__ Cm,
             int M, int N, int K) {
    __shared__ unsigned As[16][136];   // [k][m], tf32 bits
    __shared__ unsigned Bs[16][136];   // [k][n], tf32 bits
    int tid = threadIdx.x;
    int bm = blockIdx.y, bn = blockIdx.x;
    const float* Ab = A  + (size_t)bm * 128 * K;
    const float* Bb = Bm + (size_t)bn * 128;

    int warp = tid >> 5, lane = tid & 31;
    int wr = warp & 3, wc = warp >> 2;      // 4 x 2 warp grid
    int grp = lane >> 2, tig = lane & 3;
    int m0 = wr * 32, n0 = wc * 64;

    float acc[2][8][4];
    #pragma unroll
    for (int mm = 0; mm < 2; mm++)
        #pragma unroll
        for (int nn = 0; nn < 8; nn++)
            #pragma unroll
            for (int r = 0; r < 4; r++) acc[mm][nn][r] = 0.f;

    int arow = tid >> 2;            // 0..63
    int acol = (tid & 3) * 4;       // 0,4,8,12
    int brow = tid >> 5;            // 0..7
    int bcol = (tid & 31) * 4;      // 0..124

    // prefetch first tile into registers
    float4 a0 = *(const float4*)(Ab + (size_t)arow * K + acol);
    float4 a1 = *(const float4*)(Ab + (size_t)(arow + 64) * K + acol);
    float4 b0 = *(const float4*)(Bb + (size_t)brow * N + bcol);
    float4 b1 = *(const float4*)(Bb + (size_t)(brow + 8) * N + bcol);

    for (int kt = 0; kt < K; kt += 16) {
        // deposit current tile into smem (cvt to tf32 bits)
        As[acol + 0][arow] = f2tf(a0.x); As[acol + 1][arow] = f2tf(a0.y);
        As[acol + 2][arow] = f2tf(a0.z); As[acol + 3][arow] = f2tf(a0.w);
        As[acol + 0][arow + 64] = f2tf(a1.x); As[acol + 1][arow + 64] = f2tf(a1.y);
        As[acol + 2][arow + 64] = f2tf(a1.z); As[acol + 3][arow + 64] = f2tf(a1.w);
        {
            uint4 tb0 = make_uint4(f2tf(b0.x), f2tf(b0.y), f2tf(b0.z), f2tf(b0.w));
            uint4 tb1 = make_uint4(f2tf(b1.x), f2tf(b1.y), f2tf(b1.z), f2tf(b1.w));
            *(uint4*)&Bs[brow][bcol]     = tb0;
            *(uint4*)&Bs[brow + 8][bcol] = tb1;
        }
        __syncthreads();

        // issue global loads for NEXT tile before computing this one
        int kn = kt + 16;
        if (kn < K) {
            a0 = *(const float4*)(Ab + (size_t)arow * K + kn + acol);
            a1 = *(const float4*)(Ab + (size_t)(arow + 64) * K + kn + acol);
            b0 = *(const float4*)(Bb + (size_t)(kn + brow) * N + bcol);
            b1 = *(const float4*)(Bb + (size_t)(kn + brow + 8) * N + bcol);
        }

        // two k8 mma steps per BK=16 tile
        #pragma unroll
        for (int ks = 0; ks < 2; ks++) {
            int k0 = ks * 8;
            unsigned afr[2][4];
            #pragma unroll
            for (int mm = 0; mm < 2; mm++) {
                int mb = m0 + mm * 16 + grp;
                afr[mm][0] = As[k0 + tig][mb];
                afr[mm][1] = As[k0 + tig][mb + 8];
                afr[mm][2] = As[k0 + tig + 4][mb];
                afr[mm][3] = As[k0 + tig + 4][mb + 8];
            }
            #pragma unroll
            for (int nn = 0; nn < 8; nn++) {
                int nb = n0 + nn * 8 + grp;
                unsigned bf0 = Bs[k0 + tig][nb];
                unsigned bf1 = Bs[k0 + tig + 4][nb];
                mma_tf32(acc[0][nn], afr[0], bf0, bf1);
                mma_tf32(acc[1][nn], afr[1], bf0, bf1);
            }
        }
        __syncthreads();
    }

    // epilogue: per mma tile, rows (grp, grp+8), cols (2tig, 2tig+1) -> float2
    #pragma unroll
    for (int mm = 0; mm < 2; mm++) {
        int rlo = bm * 128 + m0 + mm * 16 + grp;
        int rhi = rlo + 8;
        #pragma unroll
        for (int nn = 0; nn < 8; nn++) {
            int col = bn * 128 + n0 + nn * 8 + 2 * tig;
            size_t offL = (size_t)rlo * N + col;
            size_t offH = (size_t)rhi * N + col;
            float2 vl = make_float2(acc[mm][nn][0], acc[mm][nn][1]);
            float2 vh = make_float2(acc[mm][nn][2], acc[mm][nn][3]);
            if (EPI == 1) {
                float2 rl = *(const float2*)(Res + offL);
                float2 rh = *(const float2*)(Res + offH);
                vl.x += rl.x; vl.y += rl.y;
                vh.x += rh.x; vh.y += rh.y;
            }
            if (EPI == 2) {
                vl.x = gelu_f(vl.x); vl.y = gelu_f(vl.y);
                vh.x = gelu_f(vh.x); vh.y = gelu_f(vh.y);
            }
            *(float2*)(Cm + offL) = vl;
            *(float2*)(Cm + offH) = vh;
        }
    }
}

// ---------------------------------------------------------------------------
// Flash attention (fp32): grid (T/64, H, B), 256 threads (16x16), 64-row Q tile.
// Streams 64-row K/V tiles with online softmax. qkv layout: [BT, 3C].
// ---------------------------------------------------------------------------
#define ATTN_SMEM ((3 * 64 * 68 + 64 * 65) * 4)

__global__ void __launch_bounds__(256, 2)
attn_kernel(const float* __restrict__ qkv, float* __restrict__ out) {
    extern __shared__ float smem[];
    float* Qt = smem;                 // [64 d][68]  (d-major, transposed)
    float* Kt = Qt + 64 * 68;         // [64 d][68]
    float* Vs = Kt + 64 * 68;         // [64 c][68]  (row-major)
    float* St = Vs + 64 * 68;         // [64 c][65]  (transposed P)

    int qt = blockIdx.x, h = blockIdx.y, b = blockIdx.z;
    int tid = threadIdx.x, tx = tid & 15, ty = tid >> 4;
    int qbase = qt * 64;
    const size_t rs = 3 * C_;
    const float* qptr = qkv + (size_t)b * T_ * rs + h * HD_;
    const float* kptr = qptr + C_;
    const float* vptr = qptr + 2 * C_;

    // load Q tile transposed: Qt[d][r]
    {
        int r = tid >> 4;             // 0..15
        int d = (tid & 15) * 4;       // 0..60
        #pragma unroll
        for (int i = 0; i < 4; i++) {
            int rr = r + 16 * i;
            float4 q4 = *(const float4*)(qptr + (size_t)(qbase + rr) * rs + d);
            Qt[(d + 0) * 68 + rr] = q4.x; Qt[(d + 1) * 68 + rr] = q4.y;
            Qt[(d + 2) * 68 + rr] = q4.z; Qt[(d + 3) * 68 + rr] = q4.w;
        }
    }

    float m_[4], l_[4], o[4][4];
    #pragma unroll
    for (int i = 0; i < 4; i++) {
        m_[i] = -1e30f; l_[i] = 0.f;
        #pragma unroll
        for (int j = 0; j < 4; j++) o[i][j] = 0.f;
    }
    int r0 = ty * 4, c0 = tx * 4;

    for (int kt = 0; kt <= qt; kt++) {
        int kbase = kt * 64;
        __syncthreads();   // prior PV reads of Kt/Vs/St complete
        {
            int r = tid >> 4;
            int d = (tid & 15) * 4;
            #pragma unroll
            for (int i = 0; i < 4; i++) {
                int rr = r + 16 * i;
                float4 k4 = *(const float4*)(kptr + (size_t)(kbase + rr) * rs + d);
                Kt[(d + 0) * 68 + rr] = k4.x; Kt[(d + 1) * 68 + rr] = k4.y;
                Kt[(d + 2) * 68 + rr] = k4.z; Kt[(d + 3) * 68 + rr] = k4.w;
                float4 v4 = *(const float4*)(vptr + (size_t)(kbase + rr) * rs + d);
                *(float4*)&Vs[rr * 68 + d] = v4;
            }
        }
        __syncthreads();

        // S = Q @ K^T (4x4 per thread)
        float s[4][4];
        #pragma unroll
        for (int i = 0; i < 4; i++)
            #pragma unroll
            for (int j = 0; j < 4; j++) s[i][j] = 0.f;
        #pragma unroll 4
        for (int d = 0; d < 64; d++) {
            float4 q4 = *(const float4*)&Qt[d * 68 + r0];
            float4 k4 = *(const float4*)&Kt[d * 68 + c0];
            float qa[4] = {q4.x, q4.y, q4.z, q4.w};
            float ka[4] = {k4.x, k4.y, k4.z, k4.w};
            #pragma unroll
            for (int i = 0; i < 4; i++)
                #pragma unroll
                for (int j = 0; j < 4; j++) s[i][j] += qa[i] * ka[j];
        }
        bool diag = (kt == qt);
        #pragma unroll
        for (int i = 0; i < 4; i++)
            #pragma unroll
            for (int j = 0; j < 4; j++) {
                s[i][j] *= 0.125f;  // 1/sqrt(64)
                if (diag && (c0 + j) > (r0 + i)) s[i][j] = -1e30f;
            }

        // online softmax update (row stats replicated across the 16 tx lanes)
        #pragma unroll
        for (int i = 0; i < 4; i++) {
            float mx = fmaxf(fmaxf(s[i][0], s[i][1]), fmaxf(s[i][2], s[i][3]));
            #pragma unroll
            for (int msk = 8; msk; msk >>= 1)
                mx = fmaxf(mx, __shfl_xor_sync(0xffffffffu, mx, msk));
            float mnew  = fmaxf(m_[i], mx);
            float alpha = expf(m_[i] - mnew);
            float rsum = 0.f;
            #pragma unroll
            for (int j = 0; j < 4; j++) {
                float p = expf(s[i][j] - mnew);
                s[i][j] = p; rsum += p;
            }
            #pragma unroll
            for (int msk = 8; msk; msk >>= 1)
                rsum += __shfl_xor_sync(0xffffffffu, rsum, msk);
            l_[i] = l_[i] * alpha + rsum;
            m_[i] = mnew;
            #pragma unroll
            for (int j = 0; j < 4; j++) o[i][j] *= alpha;
        }

        // store P transposed: St[c][r]
        #pragma unroll
        for (int i = 0; i < 4; i++)
            #pragma unroll
            for (int j = 0; j < 4; j++)
                St[(c0 + j) * 65 + r0 + i] = s[i][j];
        __syncthreads();

        // O += P @ V  (thread's output cols = c0..c0+3 of head dim)
        #pragma unroll 4
        for (int c = 0; c < 64; c++) {
            float p0 = St[c * 65 + r0 + 0];
            float p1 = St[c * 65 + r0 + 1];
            float p2 = St[c * 65 + r0 + 2];
            float p3 = St[c * 65 + r0 + 3];
            float4 v4 = *(const float4*)&Vs[c * 68 + c0];
            o[0][0] += p0 * v4.x; o[0][1] += p0 * v4.y; o[0][2] += p0 * v4.z; o[0][3] += p0 * v4.w;
            o[1][0] += p1 * v4.x; o[1][1] += p1 * v4.y; o[1][2] += p1 * v4.z; o[1][3] += p1 * v4.w;
            o[2][0] += p2 * v4.x; o[2][1] += p2 * v4.y; o[2][2] += p2 * v4.z; o[2][3] += p2 * v4.w;
            o[3][0] += p3 * v4.x; o[3][1] += p3 * v4.y; o[3][2] += p3 * v4.z; o[3][3] += p3 * v4.w;
        }
    }

    #pragma unroll
    for (int i = 0; i < 4; i++) {
        float inv = 1.f / l_[i];
        float4 r4 = make_float4(o[i][0] * inv, o[i][1] * inv, o[i][2] * inv, o[i][3] * inv);
        *(float4*)&out[(size_t)(b * T_ + qbase + r0 + i) * C_ + h * HD_ + c0] = r4;
    }
}

// ---------------------------------------------------------------------------
extern "C" void kernel_launch(void* const* d_in, const int* in_sizes, int n_in,
                              void* d_out, int out_size) {
    const float* x      = (const float*)d_in[0];
    const float* ln1_g  = (const float*)d_in[1];
    const float* ln1_b  = (const float*)d_in[2];
    const float* W_qkv  = (const float*)d_in[3];
    const float* W_attn = (const float*)d_in[4];
    const float* ln2_g  = (const float*)d_in[5];
    const float* ln2_b  = (const float*)d_in[6];
    const float* W_fc   = (const float*)d_in[7];
    const float* W_mlp  = (const float*)d_in[8];
    float* out = (float*)d_out;

    float *ln, *qkv, *att, *x2, *hb;
    cudaGetSymbolAddress((void**)&ln,  g_ln);
    cudaGetSymbolAddress((void**)&qkv, g_qkv);
    cudaGetSymbolAddress((void**)&att, g_att);
    cudaGetSymbolAddress((void**)&x2,  g_x2);
    cudaGetSymbolAddress((void**)&hb,  g_hbuf);

    cudaFuncSetAttribute(attn_kernel, cudaFuncAttributeMaxDynamicSharedMemorySize, ATTN_SMEM);

    // 1. ln1
    ln_kernel<<<BT_, 256>>>(x, ln1_g, ln1_b, ln);
    // 2. qkv = ln1 @ W_qkv  [4096,768]x[768,2304]
    sgemm_kernel<0><<<dim3(3 * C_ / 128, BT_ / 128), 256>>>(ln, W_qkv, nullptr, qkv, BT_, 3 * C_, C_);
    // 3. flash attention
    attn_kernel<<<dim3(T_ / 64, H_, B_), 256, ATTN_SMEM>>>(qkv, att);
    // 4. x2 = x + att @ W_attn_proj
    sgemm_kernel<1><<<dim3(C_ / 128, BT_ / 128), 256>>>(att, W_attn, x, x2, BT_, C_, C_);
    // 5. ln2
    ln_kernel<<<BT_, 256>>>(x2, ln2_g, ln2_b, ln);
    // 6. h = gelu(ln2 @ W_fc)  [4096,768]x[768,3072]
    sgemm_kernel<2><<<dim3(4 * C_ / 128, BT_ / 128), 256>>>(ln, W_fc, nullptr, hb, BT_, 4 * C_, C_);
    // 7. out = x2 + h @ W_mlp_proj  [4096,3072]x[3072,768]
    sgemm_kernel<1><<<dim3(C_ / 128, BT_ / 128), 256>>>(hb, W_mlp, x2, out, BT_, C_, 4 * C_);
}

// round 7
// speedup vs baseline: 2.4113x; 1.4345x over previous
#include <cuda_runtime.h>
#include <math.h>

#define B_  2
#define T_  2048
#define C_  768
#define H_  12
#define HD_ 64
#define BT_ (B_*T_)   // 4096

static __device__ float g_ln[BT_ * C_];          // layernorm output (reused ln1/ln2)
static __device__ float g_qkv[BT_ * 3 * C_];     // qkv projections
static __device__ float g_att[BT_ * C_];         // attention output (pre-proj)
static __device__ float g_x2[BT_ * C_];          // x + attn branch
static __device__ float g_hbuf[BT_ * 4 * C_];    // gelu(fc) activations

// ---------------------------------------------------------------------------
// helpers
// ---------------------------------------------------------------------------
__device__ __forceinline__ unsigned f2tf(float f) {
    unsigned u;
    asm("cvt.rna.tf32.f32 %0, %1;" : "=r"(u) : "f"(f));
    return u;
}

__device__ __forceinline__ void mma_tf32(float* c, const unsigned* a,
                                         unsigned b0, unsigned b1) {
    asm volatile(
        "mma.sync.aligned.m16n8k8.row.col.f32.tf32.tf32.f32 "
        "{%0,%1,%2,%3}, {%4,%5,%6,%7}, {%8,%9}, {%0,%1,%2,%3};"
        : "+f"(c[0]), "+f"(c[1]), "+f"(c[2]), "+f"(c[3])
        : "r"(a[0]), "r"(a[1]), "r"(a[2]), "r"(a[3]), "r"(b0), "r"(b1));
}

__device__ __forceinline__ float gelu_f(float v) {
    return 0.5f * v * (1.f + erff(v * 0.70710678118f));
}

// ---------------------------------------------------------------------------
// LayerNorm: one block per row (C=768 = 3*256)
// ---------------------------------------------------------------------------
__global__ void ln_kernel(const float* __restrict__ x, const float* __restrict__ g,
                          const float* __restrict__ bia, float* __restrict__ out) {
    int row = blockIdx.x;
    const float* xr = x + (size_t)row * C_;
    int t = threadIdx.x;
    float v0 = xr[t], v1 = xr[t + 256], v2 = xr[t + 512];
    float s = v0 + v1 + v2;
    float ss = v0 * v0 + v1 * v1 + v2 * v2;
    #pragma unroll
    for (int m = 16; m; m >>= 1) {
        s  += __shfl_xor_sync(0xffffffffu, s,  m);
        ss += __shfl_xor_sync(0xffffffffu, ss, m);
    }
    __shared__ float sm1[8], sm2[8];
    int w = t >> 5, l = t & 31;
    if (l == 0) { sm1[w] = s; sm2[w] = ss; }
    __syncthreads();
    if (w == 0) {
        s = sm1[l & 7]; ss = sm2[l & 7];
        #pragma unroll
        for (int m = 4; m; m >>= 1) {
            s  += __shfl_xor_sync(0xffffffffu, s,  m);
            ss += __shfl_xor_sync(0xffffffffu, ss, m);
        }
        if (l == 0) { sm1[0] = s; sm2[0] = ss; }
    }
    __syncthreads();
    float mean = sm1[0] * (1.0f / C_);
    float var  = sm2[0] * (1.0f / C_) - mean * mean;
    float inv  = rsqrtf(var + 1e-5f);
    float* orow = out + (size_t)row * C_;
    orow[t]       = (v0 - mean) * inv * g[t]       + bia[t];
    orow[t + 256] = (v1 - mean) * inv * g[t + 256] + bia[t + 256];
    orow[t + 512] = (v2 - mean) * inv * g[t + 512] + bia[t + 512];
}

// ---------------------------------------------------------------------------
// TF32 tensor-core GEMM: C = A[M,K] @ B[K,N], 128x128 block tile, BK=16,
// DOUBLE-BUFFERED smem (one __syncthreads per k-tile).
// 8 warps in 4x2: warp tile 32(m) x 64(n) = 2 x 8 mma tiles of m16n8k8.
// EPI: 0 = plain, 1 = +Res (residual), 2 = exact GELU.
// ---------------------------------------------------------------------------
template <int EPI>
__global__ void __launch_bounds__(256, 2)
sgemm_kernel(const float* __restrict__ A, const float* __restrict__ Bm,
             const float* __restrict__ Res, float* __restrict__ Cm,
             int M, int N, int K) {
    __shared__ unsigned As[2][16][136];   // [buf][k][m], tf32 bits
    __shared__ unsigned Bs[2][16][136];   // [buf][k][n], tf32 bits
    int tid = threadIdx.x;
    int bm = blockIdx.y, bn = blockIdx.x;
    const float* Ab = A  + (size_t)bm * 128 * K;
    const float* Bb = Bm + (size_t)bn * 128;

    int warp = tid >> 5, lane = tid & 31;
    int wr = warp & 3, wc = warp >> 2;      // 4 x 2 warp grid
    int grp = lane >> 2, tig = lane & 3;
    int m0 = wr * 32, n0 = wc * 64;

    float acc[2][8][4];
    #pragma unroll
    for (int mm = 0; mm < 2; mm++)
        #pragma unroll
        for (int nn = 0; nn < 8; nn++)
            #pragma unroll
            for (int r = 0; r < 4; r++) acc[mm][nn][r] = 0.f;

    int arow = tid >> 2;            // 0..63
    int acol = (tid & 3) * 4;       // 0,4,8,12
    int brow = tid >> 5;            // 0..7
    int bcol = (tid & 31) * 4;      // 0..124

    // load + deposit tile 0 into buffer 0
    float4 a0 = *(const float4*)(Ab + (size_t)arow * K + acol);
    float4 a1 = *(const float4*)(Ab + (size_t)(arow + 64) * K + acol);
    float4 b0 = *(const float4*)(Bb + (size_t)brow * N + bcol);
    float4 b1 = *(const float4*)(Bb + (size_t)(brow + 8) * N + bcol);
    As[0][acol + 0][arow] = f2tf(a0.x); As[0][acol + 1][arow] = f2tf(a0.y);
    As[0][acol + 2][arow] = f2tf(a0.z); As[0][acol + 3][arow] = f2tf(a0.w);
    As[0][acol + 0][arow + 64] = f2tf(a1.x); As[0][acol + 1][arow + 64] = f2tf(a1.y);
    As[0][acol + 2][arow + 64] = f2tf(a1.z); As[0][acol + 3][arow + 64] = f2tf(a1.w);
    {
        uint4 tb0 = make_uint4(f2tf(b0.x), f2tf(b0.y), f2tf(b0.z), f2tf(b0.w));
        uint4 tb1 = make_uint4(f2tf(b1.x), f2tf(b1.y), f2tf(b1.z), f2tf(b1.w));
        *(uint4*)&Bs[0][brow][bcol]     = tb0;
        *(uint4*)&Bs[0][brow + 8][bcol] = tb1;
    }
    __syncthreads();

    int ntile = K >> 4;
    for (int it = 0; it < ntile; it++) {
        int cur = it & 1, nxt = cur ^ 1;
        int kn = (it + 1) << 4;
        bool more = kn < K;
        if (more) {
            a0 = *(const float4*)(Ab + (size_t)arow * K + kn + acol);
            a1 = *(const float4*)(Ab + (size_t)(arow + 64) * K + kn + acol);
            b0 = *(const float4*)(Bb + (size_t)(kn + brow) * N + bcol);
            b1 = *(const float4*)(Bb + (size_t)(kn + brow + 8) * N + bcol);
        }

        // two k8 mma steps per BK=16 tile
        #pragma unroll
        for (int ks = 0; ks < 2; ks++) {
            int k0 = ks * 8;
            unsigned afr[2][4];
            #pragma unroll
            for (int mm = 0; mm < 2; mm++) {
                int mb = m0 + mm * 16 + grp;
                afr[mm][0] = As[cur][k0 + tig][mb];
                afr[mm][1] = As[cur][k0 + tig][mb + 8];
                afr[mm][2] = As[cur][k0 + tig + 4][mb];
                afr[mm][3] = As[cur][k0 + tig + 4][mb + 8];
            }
            #pragma unroll
            for (int nn = 0; nn < 8; nn++) {
                int nb = n0 + nn * 8 + grp;
                unsigned bf0 = Bs[cur][k0 + tig][nb];
                unsigned bf1 = Bs[cur][k0 + tig + 4][nb];
                mma_tf32(acc[0][nn], afr[0], bf0, bf1);
                mma_tf32(acc[1][nn], afr[1], bf0, bf1);
            }
        }

        if (more) {
            As[nxt][acol + 0][arow] = f2tf(a0.x); As[nxt][acol + 1][arow] = f2tf(a0.y);
            As[nxt][acol + 2][arow] = f2tf(a0.z); As[nxt][acol + 3][arow] = f2tf(a0.w);
            As[nxt][acol + 0][arow + 64] = f2tf(a1.x); As[nxt][acol + 1][arow + 64] = f2tf(a1.y);
            As[nxt][acol + 2][arow + 64] = f2tf(a1.z); As[nxt][acol + 3][arow + 64] = f2tf(a1.w);
            uint4 tb0 = make_uint4(f2tf(b0.x), f2tf(b0.y), f2tf(b0.z), f2tf(b0.w));
            uint4 tb1 = make_uint4(f2tf(b1.x), f2tf(b1.y), f2tf(b1.z), f2tf(b1.w));
            *(uint4*)&Bs[nxt][brow][bcol]     = tb0;
            *(uint4*)&Bs[nxt][brow + 8][bcol] = tb1;
        }
        __syncthreads();
    }

    // epilogue: per mma tile, rows (grp, grp+8), cols (2tig, 2tig+1) -> float2
    #pragma unroll
    for (int mm = 0; mm < 2; mm++) {
        int rlo = bm * 128 + m0 + mm * 16 + grp;
        int rhi = rlo + 8;
        #pragma unroll
        for (int nn = 0; nn < 8; nn++) {
            int col = bn * 128 + n0 + nn * 8 + 2 * tig;
            size_t offL = (size_t)rlo * N + col;
            size_t offH = (size_t)rhi * N + col;
            float2 vl = make_float2(acc[mm][nn][0], acc[mm][nn][1]);
            float2 vh = make_float2(acc[mm][nn][2], acc[mm][nn][3]);
            if (EPI == 1) {
                float2 rl = *(const float2*)(Res + offL);
                float2 rh = *(const float2*)(Res + offH);
                vl.x += rl.x; vl.y += rl.y;
                vh.x += rh.x; vh.y += rh.y;
            }
            if (EPI == 2) {
                vl.x = gelu_f(vl.x); vl.y = gelu_f(vl.y);
                vh.x = gelu_f(vh.x); vh.y = gelu_f(vh.y);
            }
            *(float2*)(Cm + offL) = vl;
            *(float2*)(Cm + offH) = vh;
        }
    }
}

// ---------------------------------------------------------------------------
// TF32-MMA flash attention: grid (T/128, H, B), 256 threads = 8 warps.
// Q tile 128 rows, warp w owns rows 16w..16w+15 (Q kept in A-fragments,
// pre-scaled by 1/8). K/V tiles 64 rows streamed; online softmax on
// C-fragments; P round-trips through smem as tf32 for the PV A-operand.
// K stored transposed [d][c], V row-major [c][d], P [r][c], pad 72
// (8*tig+grp bank pattern -> conflict-free fragment loads).
// ---------------------------------------------------------------------------
#define AT_PAD 72
#define ATTN_SMEM ((64 * AT_PAD + 64 * AT_PAD + 128 * AT_PAD) * 4)

__global__ void __launch_bounds__(256)
attn_kernel(const float* __restrict__ qkv, float* __restrict__ out) {
    extern __shared__ unsigned smem_u[];
    unsigned* Kt = smem_u;                 // [64 d][AT_PAD]  (transposed)
    unsigned* Vs = Kt + 64 * AT_PAD;       // [64 c][AT_PAD]
    unsigned* Ps = Vs + 64 * AT_PAD;       // [128 r][AT_PAD]

    int qt = blockIdx.x, h = blockIdx.y, b = blockIdx.z;
    int tid = threadIdx.x, warp = tid >> 5, lane = tid & 31;
    int grp = lane >> 2, tig = lane & 3;
    int qbase = qt * 128;
    const size_t rs = 3 * C_;
    const float* base = qkv + (size_t)b * T_ * rs + h * HD_;
    const float* kptr = base + C_;
    const float* vptr = base + 2 * C_;

    // Q fragments (pre-scaled by 1/sqrt(64) = 0.125)
    unsigned qf[8][4];
    {
        const float* q0 = base + (size_t)(qbase + warp * 16 + grp) * rs;
        const float* q1 = q0 + 8 * rs;
        #pragma unroll
        for (int kc = 0; kc < 8; kc++) {
            qf[kc][0] = f2tf(0.125f * q0[kc * 8 + tig]);
            qf[kc][1] = f2tf(0.125f * q1[kc * 8 + tig]);
            qf[kc][2] = f2tf(0.125f * q0[kc * 8 + tig + 4]);
            qf[kc][3] = f2tf(0.125f * q1[kc * 8 + tig + 4]);
        }
    }

    float oacc[8][4];
    #pragma unroll
    for (int nt = 0; nt < 8; nt++)
        #pragma unroll
        for (int r = 0; r < 4; r++) oacc[nt][r] = 0.f;
    float m0 = -1e30f, m1 = -1e30f, l0 = 0.f, l1 = 0.f;

    int lr  = tid >> 2;          // 0..63 token row for K/V loads
    int ld0 = (tid & 3) * 16;    // starting d for this thread
    int row_g = qbase + warp * 16 + grp;   // global q row for regs 0,1 (+8 for 2,3)
    int nkt = qt * 2 + 2;

    for (int kt = 0; kt < nkt; kt++) {
        int kbase = kt * 64;
        __syncthreads();   // prior reads of Kt/Vs/Ps complete
        #pragma unroll
        for (int i = 0; i < 4; i++) {
            int d = ld0 + 4 * i;
            float4 k4 = *(const float4*)(kptr + (size_t)(kbase + lr) * rs + d);
            Kt[(d + 0) * AT_PAD + lr] = f2tf(k4.x);
            Kt[(d + 1) * AT_PAD + lr] = f2tf(k4.y);
            Kt[(d + 2) * AT_PAD + lr] = f2tf(k4.z);
            Kt[(d + 3) * AT_PAD + lr] = f2tf(k4.w);
            float4 v4 = *(const float4*)(vptr + (size_t)(kbase + lr) * rs + d);
            uint4 tv = make_uint4(f2tf(v4.x), f2tf(v4.y), f2tf(v4.z), f2tf(v4.w));
            *(uint4*)&Vs[lr * AT_PAD + d] = tv;
        }
        __syncthreads();

        // S = Q @ K^T  (K^T[k][n] = Kt[k][n] directly)
        float sacc[8][4];
        #pragma unroll
        for (int nt = 0; nt < 8; nt++)
            #pragma unroll
            for (int r = 0; r < 4; r++) sacc[nt][r] = 0.f;
        #pragma unroll
        for (int kc = 0; kc < 8; kc++) {
            #pragma unroll
            for (int nt = 0; nt < 8; nt++) {
                unsigned bf0 = Kt[(kc * 8 + tig) * AT_PAD + nt * 8 + grp];
                unsigned bf1 = Kt[(kc * 8 + tig + 4) * AT_PAD + nt * 8 + grp];
                mma_tf32(sacc[nt], qf[kc], bf0, bf1);
            }
        }

        // causal mask (only tiles touching/above the diagonal band)
        if (kbase + 63 > qbase) {
            #pragma unroll
            for (int nt = 0; nt < 8; nt++) {
                int col = kbase + nt * 8 + 2 * tig;
                if (col     > row_g)     sacc[nt][0] = -1e30f;
                if (col + 1 > row_g)     sacc[nt][1] = -1e30f;
                if (col     > row_g + 8) sacc[nt][2] = -1e30f;
                if (col + 1 > row_g + 8) sacc[nt][3] = -1e30f;
            }
        }

        // online softmax (rows grp and grp+8; reduce across quad lanes)
        float mx0 = -1e30f, mx1 = -1e30f;
        #pragma unroll
        for (int nt = 0; nt < 8; nt++) {
            mx0 = fmaxf(mx0, fmaxf(sacc[nt][0], sacc[nt][1]));
            mx1 = fmaxf(mx1, fmaxf(sacc[nt][2], sacc[nt][3]));
        }
        mx0 = fmaxf(mx0, __shfl_xor_sync(0xffffffffu, mx0, 1));
        mx0 = fmaxf(mx0, __shfl_xor_sync(0xffffffffu, mx0, 2));
        mx1 = fmaxf(mx1, __shfl_xor_sync(0xffffffffu, mx1, 1));
        mx1 = fmaxf(mx1, __shfl_xor_sync(0xffffffffu, mx1, 2));
        float mn0 = fmaxf(m0, mx0), mn1 = fmaxf(m1, mx1);
        float al0 = __expf(m0 - mn0), al1 = __expf(m1 - mn1);
        float s0 = 0.f, s1 = 0.f;
        #pragma unroll
        for (int nt = 0; nt < 8; nt++) {
            float p0 = __expf(sacc[nt][0] - mn0);
            float p1 = __expf(sacc[nt][1] - mn0);
            float p2 = __expf(sacc[nt][2] - mn1);
            float p3 = __expf(sacc[nt][3] - mn1);
            sacc[nt][0] = p0; sacc[nt][1] = p1; sacc[nt][2] = p2; sacc[nt][3] = p3;
            s0 += p0 + p1; s1 += p2 + p3;
        }
        s0 += __shfl_xor_sync(0xffffffffu, s0, 1);
        s0 += __shfl_xor_sync(0xffffffffu, s0, 2);
        s1 += __shfl_xor_sync(0xffffffffu, s1, 1);
        s1 += __shfl_xor_sync(0xffffffffu, s1, 2);
        l0 = l0 * al0 + s0; l1 = l1 * al1 + s1;
        m0 = mn0; m1 = mn1;
        #pragma unroll
        for (int nt = 0; nt < 8; nt++) {
            oacc[nt][0] *= al0; oacc[nt][1] *= al0;
            oacc[nt][2] *= al1; oacc[nt][3] *= al1;
        }

        // P -> smem (tf32 bits) for PV A-operand
        {
            int pr = warp * 16 + grp;
            #pragma unroll
            for (int nt = 0; nt < 8; nt++) {
                Ps[pr * AT_PAD + nt * 8 + 2 * tig]           = f2tf(sacc[nt][0]);
                Ps[pr * AT_PAD + nt * 8 + 2 * tig + 1]       = f2tf(sacc[nt][1]);
                Ps[(pr + 8) * AT_PAD + nt * 8 + 2 * tig]     = f2tf(sacc[nt][2]);
                Ps[(pr + 8) * AT_PAD + nt * 8 + 2 * tig + 1] = f2tf(sacc[nt][3]);
            }
        }
        __syncthreads();

        // O += P @ V
        #pragma unroll
        for (int kc = 0; kc < 8; kc++) {
            unsigned af[4];
            int pr = warp * 16 + grp;
            af[0] = Ps[pr * AT_PAD + kc * 8 + tig];
            af[1] = Ps[(pr + 8) * AT_PAD + kc * 8 + tig];
            af[2] = Ps[pr * AT_PAD + kc * 8 + tig + 4];
            af[3] = Ps[(pr + 8) * AT_PAD + kc * 8 + tig + 4];
            #pragma unroll
            for (int nt = 0; nt < 8; nt++) {
                unsigned bf0 = Vs[(kc * 8 + tig) * AT_PAD + nt * 8 + grp];
                unsigned bf1 = Vs[(kc * 8 + tig + 4) * AT_PAD + nt * 8 + grp];
                mma_tf32(oacc[nt], af, bf0, bf1);
            }
        }
    }

    // epilogue
    float inv0 = 1.f / l0, inv1 = 1.f / l1;
    float* o0 = out + (size_t)(b * T_ + row_g) * C_ + h * HD_;
    float* o1 = o0 + 8 * C_;
    #pragma unroll
    for (int nt = 0; nt < 8; nt++) {
        int c = nt * 8 + 2 * tig;
        o0[c]     = oacc[nt][0] * inv0;
        o0[c + 1] = oacc[nt][1] * inv0;
        o1[c]     = oacc[nt][2] * inv1;
        o1[c + 1] = oacc[nt][3] * inv1;
    }
}

// ---------------------------------------------------------------------------
extern "C" void kernel_launch(void* const* d_in, const int* in_sizes, int n_in,
                              void* d_out, int out_size) {
    const float* x      = (const float*)d_in[0];
    const float* ln1_g  = (const float*)d_in[1];
    const float* ln1_b  = (const float*)d_in[2];
    const float* W_qkv  = (const float*)d_in[3];
    const float* W_attn = (const float*)d_in[4];
    const float* ln2_g  = (const float*)d_in[5];
    const float* ln2_b  = (const float*)d_in[6];
    const float* W_fc   = (const float*)d_in[7];
    const float* W_mlp  = (const float*)d_in[8];
    float* out = (float*)d_out;

    float *ln, *qkv, *att, *x2, *hb;
    cudaGetSymbolAddress((void**)&ln,  g_ln);
    cudaGetSymbolAddress((void**)&qkv, g_qkv);
    cudaGetSymbolAddress((void**)&att, g_att);
    cudaGetSymbolAddress((void**)&x2,  g_x2);
    cudaGetSymbolAddress((void**)&hb,  g_hbuf);

    cudaFuncSetAttribute(attn_kernel, cudaFuncAttributeMaxDynamicSharedMemorySize, ATTN_SMEM);

    // 1. ln1
    ln_kernel<<<BT_, 256>>>(x, ln1_g, ln1_b, ln);
    // 2. qkv = ln1 @ W_qkv  [4096,768]x[768,2304]
    sgemm_kernel<0><<<dim3(3 * C_ / 128, BT_ / 128), 256>>>(ln, W_qkv, nullptr, qkv, BT_, 3 * C_, C_);
    // 3. flash attention (TF32 MMA)
    attn_kernel<<<dim3(T_ / 128, H_, B_), 256, ATTN_SMEM>>>(qkv, att);
    // 4. x2 = x + att @ W_attn_proj
    sgemm_kernel<1><<<dim3(C_ / 128, BT_ / 128), 256>>>(att, W_attn, x, x2, BT_, C_, C_);
    // 5. ln2
    ln_kernel<<<BT_, 256>>>(x2, ln2_g, ln2_b, ln);
    // 6. h = gelu(ln2 @ W_fc)  [4096,768]x[768,3072]
    sgemm_kernel<2><<<dim3(4 * C_ / 128, BT_ / 128), 256>>>(ln, W_fc, nullptr, hb, BT_, 4 * C_, C_);
    // 7. out = x2 + h @ W_mlp_proj  [4096,3072]x[3072,768]
    sgemm_kernel<1><<<dim3(C_ / 128, BT_ / 128), 256>>>(hb, W_mlp, x2, out, BT_, C_, 4 * C_);
}